// round 5
// baseline (speedup 1.0000x reference)
#include <cuda_runtime.h>

// RandomShiftsAug == integer shifted gather with edge clamp:
//   out[n,c,j,i] = x[n,c, clamp(j+sy-4,0,83), clamp(i+sx-4,0,83)]
//
// R4 established: lane-contiguous scalar access + per-thread load batching.
// R5 fixes R4's leaks:
//   - 28-deep register batch didn't fit in 40 regs -> chunk 4 x (7 loads + 7
//     stores); __launch_bounds__(252,8) caps regs at 32 -> 64 warps/SM.
//   - loads use DEFAULT cache policy: the 130MB input ~fits the 126MB L2 and
//     stays resident across graph replays (R4 showed ~40% read hit).
//   - stores stay streaming (__stcs) so output writes don't evict the input.

#define N_   512
#define C_   9
#define H_   84
#define W_   84
#define PAD_ 4

#define SLICE    (H_ * W_)     // 7056
#define THREADS  252           // 3 rows x 84 cols
#define CHUNK    7
#define NCHUNK   4             // 28 rows per thread = 84 / 3

__global__ __launch_bounds__(THREADS, 8) void random_shift_pipe_kernel(
    const float* __restrict__ x,
    const int*   __restrict__ shift,
    float*       __restrict__ out)
{
    const int nc  = blockIdx.x;          // (n*C + c)
    const int n   = nc / C_;
    const int tid = threadIdx.x;

    const int i  = tid % W_;             // column, 0..83
    const int j0 = tid / W_;             // starting row, 0..2

    const int sx = __ldg(&shift[2 * n + 0]) - PAD_;   // [-4, 4]
    const int sy = __ldg(&shift[2 * n + 1]) - PAD_;

    const int srcx = min(max(i + sx, 0), W_ - 1);     // column clamp, hoisted

    const float* __restrict__ src = x   + (long)nc * SLICE + srcx;
    float*       __restrict__ dst = out + (long)nc * SLICE + i * 1;

    #pragma unroll
    for (int c = 0; c < NCHUNK; c++) {
        float v[CHUNK];
        #pragma unroll
        for (int k = 0; k < CHUNK; k++) {
            int j = j0 + 3 * (c * CHUNK + k);         // output row
            int srcy = min(max(j + sy, 0), H_ - 1);
            v[k] = src[srcy * W_];                    // default policy: L2-friendly
        }
        #pragma unroll
        for (int k = 0; k < CHUNK; k++) {
            int j = j0 + 3 * (c * CHUNK + k);
            __stcs(dst + j * W_, v[k]);               // streaming store
        }
    }
}

extern "C" void kernel_launch(void* const* d_in, const int* in_sizes, int n_in,
                              void* d_out, int out_size)
{
    const float* x     = (const float*)d_in[0];
    const int*   shift = (const int*)  d_in[1];
    float* out = (float*)d_out;

    random_shift_pipe_kernel<<<N_ * C_, THREADS>>>(x, shift, out);
}